// round 2
// baseline (speedup 1.0000x reference)
#include <cuda_runtime.h>
#include <cuda_bf16.h>

// Problem constants
#define TT 64
#define SS 64
#define BZ 128
#define EE 64
#define HH 4
#define HD 16

// Scratch (device globals; allocation-free)
__device__ __nv_bfloat16 g_wrel[128 * 64];            // rel_weight in bf16, [n][k]
__device__ float g_q[TT * BZ * EE];                   // [i][b][e]
__device__ float g_k[SS * BZ * EE];                   // [j][b][e]
__device__ float g_v[SS * BZ * EE];                   // [j][b][e]
__device__ float g_logits[TT * SS * BZ * HH];         // [i][j][b][h]

// ---------------------------------------------------------------------------
// Kernel 0: convert rel_weight fp32 [128][64] -> bf16 scratch
// ---------------------------------------------------------------------------
__global__ void k_convw(const float* __restrict__ w) {
    int t = threadIdx.x;
    #pragma unroll
    for (int it = 0; it < 32; ++it) {
        int idx = it * 256 + t;          // 8192 elements
        g_wrel[idx] = __float2bfloat16(w[idx]);
    }
}

// ---------------------------------------------------------------------------
// Kernel 1: q/k/v projections (fp32 scalar; exact)
//   q[row][e] = sum_f x[row][f] * W[e][f] + bias[e]      row = i*128+b
// Block: 256 threads handles 64 rows. Grid: 128 blocks.
// SMEM: Ws[f][192] (transposed weights) + 3 x-tiles [64][64]
// ---------------------------------------------------------------------------
__global__ __launch_bounds__(256) void k_qkv(
    const float* __restrict__ xq, const float* __restrict__ xk,
    const float* __restrict__ xv, const float* __restrict__ W,
    const float* __restrict__ bias)
{
    extern __shared__ float sm1[];
    float* Ws  = sm1;               // [64][192]
    float* xsq = sm1 + 64 * 192;    // [64][64]
    float* xsk = xsq + 64 * 64;
    float* xsv = xsk + 64 * 64;

    int t  = threadIdx.x;
    int r0 = blockIdx.x * 64;

    // stage W transposed: W[eo][f] -> Ws[f*192 + eo]   (12288 floats)
    for (int it = 0; it < 48; ++it) {
        int idx = it * 256 + t;
        int eo = idx >> 6, f = idx & 63;
        Ws[f * 192 + eo] = W[idx];
    }
    // stage x tiles (4096 floats each), contiguous
    for (int it = 0; it < 16; ++it) {
        int idx = it * 256 + t;
        xsq[idx] = xq[r0 * 64 + idx];
        xsk[idx] = xk[r0 * 64 + idx];
        xsv[idx] = xv[r0 * 64 + idx];
    }
    __syncthreads();

    int e = t & 63, rg = t >> 6;  // e: output col, rg: row group (16 rows)
    float aq[16], ak[16], av[16];
    #pragma unroll
    for (int r = 0; r < 16; ++r) { aq[r] = 0.f; ak[r] = 0.f; av[r] = 0.f; }

    for (int f = 0; f < 64; ++f) {
        float wq = Ws[f * 192 + e];
        float wk = Ws[f * 192 + 64 + e];
        float wv = Ws[f * 192 + 128 + e];
        #pragma unroll
        for (int r = 0; r < 16; ++r) {
            int row = rg * 16 + r;
            aq[r] += xsq[row * 64 + f] * wq;
            ak[r] += xsk[row * 64 + f] * wk;
            av[r] += xsv[row * 64 + f] * wv;
        }
    }
    float bq = bias[e], bk = bias[64 + e], bv = bias[128 + e];
    #pragma unroll
    for (int r = 0; r < 16; ++r) {
        int row = r0 + rg * 16 + r;
        g_q[row * 64 + e] = aq[r] + bq;
        g_k[row * 64 + e] = ak[r] + bk;
        g_v[row * 64 + e] = av[r] + bv;
    }
}

// ---------------------------------------------------------------------------
// Kernel 2 (main): fused relation GEMM (bf16 mma.sync) + logits epilogue.
// One CTA per (x=j, y=i) pair; tile rows = all 128 b. M=128, N=128, K=64.
//   logit[i=y][j=x][b][h] = (1/16) * sum_n (q[y,b,hn]+A_n+ba_n)*(k[x,b,hn]+B_n+bb_n)
// where [A|B] = relation[x,y,b,:] @ rel_weight^T.
// ---------------------------------------------------------------------------
__device__ __forceinline__ void mma16816(float c[4], const unsigned a[4],
                                         const unsigned b[2]) {
    asm volatile(
        "mma.sync.aligned.m16n8k16.row.col.f32.bf16.bf16.f32 "
        "{%0,%1,%2,%3}, {%4,%5,%6,%7}, {%8,%9}, {%0,%1,%2,%3};\n"
        : "+f"(c[0]), "+f"(c[1]), "+f"(c[2]), "+f"(c[3])
        : "r"(a[0]), "r"(a[1]), "r"(a[2]), "r"(a[3]), "r"(b[0]), "r"(b[1]));
}

__global__ __launch_bounds__(256, 2) void k_rel(
    const float* __restrict__ rel, const float* __restrict__ relbias)
{
    extern __shared__ char smraw[];
    // Phase 1 view: bf16 operands, row stride 72 bf16 (36 words) -> conflict-free frags
    unsigned* As32 = (unsigned*)smraw;                    // [128][36] words
    unsigned* Bs32 = (unsigned*)(smraw + 128 * 72 * 2);   // [128][36] words
    // Phase 2 view (aliases operands after sync): fp32 C [128][132]
    float* Cs = (float*)smraw;
    __shared__ float sbias[128];

    int t = threadIdx.x;
    int x = blockIdx.x >> 6;     // j
    int y = blockIdx.x & 63;     // i
    if (t < 128) sbias[t] = relbias[t];

    // Load relation tile: 8192 contiguous fp32, convert to bf16 in SMEM
    const float4* rp = (const float4*)(rel + (size_t)blockIdx.x * 8192);
    #pragma unroll
    for (int it = 0; it < 8; ++it) {
        float4 v = rp[it * 256 + t];
        int fidx = (it * 256 + t) * 4;
        int row = fidx >> 6, kk = fidx & 63;
        __nv_bfloat162 p0 = __floats2bfloat162_rn(v.x, v.y);
        __nv_bfloat162 p1 = __floats2bfloat162_rn(v.z, v.w);
        unsigned* dst = &As32[row * 36 + (kk >> 1)];
        dst[0] = *(unsigned*)&p0;
        dst[1] = *(unsigned*)&p1;
    }
    // Load bf16 weights: 4096 words (L2-hot)
    const unsigned* wp = (const unsigned*)g_wrel;
    #pragma unroll
    for (int it = 0; it < 16; ++it) {
        int idx = it * 256 + t;                 // word idx: n = idx>>5, khalf = idx&31
        Bs32[(idx >> 5) * 36 + (idx & 31)] = wp[idx];
    }
    __syncthreads();

    // MMA: 8 warps, warp (wm, wn) covers rows 32*wm..+31, cols 64*wn..+63
    int warp = t >> 5, lane = t & 31;
    int wm = warp & 3, wn = warp >> 2;
    int lr = lane >> 2, lc = lane & 3;

    float c[2][8][4];
    #pragma unroll
    for (int mt = 0; mt < 2; ++mt)
        #pragma unroll
        for (int nt = 0; nt < 8; ++nt)
            #pragma unroll
            for (int q4 = 0; q4 < 4; ++q4) c[mt][nt][q4] = 0.f;

    #pragma unroll
    for (int ks = 0; ks < 4; ++ks) {          // k0 = ks*16 -> word offset ks*8
        int k0w = ks * 8;
        unsigned a[2][4], b[8][2];
        #pragma unroll
        for (int mt = 0; mt < 2; ++mt) {
            int rb = wm * 32 + mt * 16;
            a[mt][0] = As32[(rb + lr) * 36 + k0w + lc];
            a[mt][1] = As32[(rb + lr + 8) * 36 + k0w + lc];
            a[mt][2] = As32[(rb + lr) * 36 + k0w + lc + 4];
            a[mt][3] = As32[(rb + lr + 8) * 36 + k0w + lc + 4];
        }
        #pragma unroll
        for (int nt = 0; nt < 8; ++nt) {
            int nb = wn * 64 + nt * 8;
            b[nt][0] = Bs32[(nb + lr) * 36 + k0w + lc];
            b[nt][1] = Bs32[(nb + lr) * 36 + k0w + lc + 4];
        }
        #pragma unroll
        for (int mt = 0; mt < 2; ++mt)
            #pragma unroll
            for (int nt = 0; nt < 8; ++nt)
                mma16816(c[mt][nt], a[mt], b[nt]);
    }
    __syncthreads();  // operands dead; reuse SMEM as Cs

    #pragma unroll
    for (int mt = 0; mt < 2; ++mt)
        #pragma unroll
        for (int nt = 0; nt < 8; ++nt) {
            int row = wm * 32 + mt * 16 + lr;
            int col = wn * 64 + nt * 8 + lc * 2;
            *(float2*)&Cs[row * 132 + col] = make_float2(c[mt][nt][0], c[mt][nt][1]);
            *(float2*)&Cs[(row + 8) * 132 + col] = make_float2(c[mt][nt][2], c[mt][nt][3]);
        }
    __syncthreads();

    // Epilogue: per row b (=tile row), per head: dot with q/k -> logits
    int b = t >> 1, half = t & 1;
    float2 outv;
    #pragma unroll
    for (int hi = 0; hi < 2; ++hi) {
        int h = half * 2 + hi;
        const float* qr = g_q + ((y * 128 + b) * 64 + h * 16);
        const float* kr = g_k + ((x * 128 + b) * 64 + h * 16);
        const float* Ar = &Cs[b * 132 + h * 16];
        const float* Br = &Cs[b * 132 + 64 + h * 16];
        const float* ba = &sbias[h * 16];
        const float* bb = &sbias[64 + h * 16];
        float acc = 0.f;
        #pragma unroll
        for (int n = 0; n < 16; ++n)
            acc += (qr[n] + Ar[n] + ba[n]) * (kr[n] + Br[n] + bb[n]);
        (&outv.x)[hi] = acc * 0.0625f;   // scaling * 1/sqrt(hd) = 1/16
    }
    // logits layout [i=y][j=x][b][h]; h-pair contiguous -> coalesced float2
    size_t obase = ((size_t)(y * 64 + x) * 128 + b) * 4 + half * 2;
    *(float2*)&g_logits[obase] = outv;
}

// ---------------------------------------------------------------------------
// Kernel 3: softmax over j + AV + out-projection. Block per b (128 blocks),
// 256 threads = (i 64) x (h 4). v[:,b,:] staged in SMEM once.
// ---------------------------------------------------------------------------
__global__ __launch_bounds__(256) void k_av(
    const float* __restrict__ Wo, const float* __restrict__ bo,
    float* __restrict__ out)
{
    extern __shared__ float sm3[];
    float* vs   = sm3;            // [64 x][64 e]
    float* Wos  = sm3 + 4096;     // [64 f][64 e]  (transposed out_weight)
    float* attn = sm3 + 8192;     // [64 i][68]

    int t = threadIdx.x;
    int b = blockIdx.x;

    for (int it = 0; it < 16; ++it) {
        int idx = it * 256 + t;   // 4096
        int xr = idx >> 6, e = idx & 63;
        vs[idx] = g_v[((size_t)xr * 128 + b) * 64 + e];
        Wos[e * 64 + xr] = Wo[idx];   // Wo[eo][f]: xr=eo, e=f -> Wos[f][eo]
    }
    __syncthreads();

    int h = t & 3, i = t >> 2;

    // softmax over j (=x), per (i, b, h)
    float l[64];
    const float* lp = g_logits + ((size_t)i * 32768 + (size_t)b * 4 + h);
    #pragma unroll
    for (int xj = 0; xj < 64; ++xj) l[xj] = lp[(size_t)xj * 512];
    float m = l[0];
    #pragma unroll
    for (int xj = 1; xj < 64; ++xj) m = fmaxf(m, l[xj]);
    float ssum = 0.f;
    #pragma unroll
    for (int xj = 0; xj < 64; ++xj) { l[xj] = __expf(l[xj] - m); ssum += l[xj]; }
    float inv = 1.f / ssum;

    // AV: acc[n] = sum_x w[x] * v[x][h*16+n]
    float acc[16];
    #pragma unroll
    for (int n = 0; n < 16; ++n) acc[n] = 0.f;
    for (int xj = 0; xj < 64; ++xj) {
        float wv = l[xj] * inv;
        const float4* vp = (const float4*)&vs[xj * 64 + h * 16];
        #pragma unroll
        for (int g = 0; g < 4; ++g) {
            float4 vv = vp[g];
            acc[4 * g + 0] += wv * vv.x;
            acc[4 * g + 1] += wv * vv.y;
            acc[4 * g + 2] += wv * vv.z;
            acc[4 * g + 3] += wv * vv.w;
        }
    }
    // stage attn row segment
    float* ap = &attn[i * 68 + h * 16];
    #pragma unroll
    for (int g = 0; g < 4; ++g)
        *(float4*)&ap[4 * g] = make_float4(acc[4 * g], acc[4 * g + 1],
                                           acc[4 * g + 2], acc[4 * g + 3]);
    __syncthreads();

    // out projection: out[i][b][e] = sum_f attn[i][f] * Wo[e][f] + bo[e]
    int i2 = t >> 2, eg = t & 3;
    float oacc[16];
    #pragma unroll
    for (int n = 0; n < 16; ++n) oacc[n] = 0.f;
    for (int f = 0; f < 64; ++f) {
        float a = attn[i2 * 68 + f];
        const float4* wp4 = (const float4*)&Wos[f * 64 + eg * 16];
        #pragma unroll
        for (int g = 0; g < 4; ++g) {
            float4 w4 = wp4[g];
            oacc[4 * g + 0] += a * w4.x;
            oacc[4 * g + 1] += a * w4.y;
            oacc[4 * g + 2] += a * w4.z;
            oacc[4 * g + 3] += a * w4.w;
        }
    }
    float* op = out + ((size_t)i2 * 128 + b) * 64 + eg * 16;
    #pragma unroll
    for (int n = 0; n < 16; ++n) op[n] = oacc[n] + bo[eg * 16 + n];
}

// ---------------------------------------------------------------------------
extern "C" void kernel_launch(void* const* d_in, const int* in_sizes, int n_in,
                              void* d_out, int out_size) {
    const float* q_in = (const float*)d_in[0];
    const float* k_in = (const float*)d_in[1];
    const float* v_in = (const float*)d_in[2];
    const float* rel  = (const float*)d_in[3];
    const float* ipw  = (const float*)d_in[4];
    const float* ipb  = (const float*)d_in[5];
    const float* rw   = (const float*)d_in[6];
    const float* rb   = (const float*)d_in[7];
    const float* ow   = (const float*)d_in[8];
    const float* ob   = (const float*)d_in[9];

    cudaFuncSetAttribute(k_qkv, cudaFuncAttributeMaxDynamicSharedMemorySize, 98304);
    cudaFuncSetAttribute(k_rel, cudaFuncAttributeMaxDynamicSharedMemorySize, 67584);
    cudaFuncSetAttribute(k_av,  cudaFuncAttributeMaxDynamicSharedMemorySize, 50176);

    k_convw<<<1, 256>>>(rw);
    k_qkv<<<128, 256, 98304>>>(q_in, k_in, v_in, ipw, ipb);
    k_rel<<<4096, 256, 67584>>>(rel, rb);
    k_av<<<128, 256, 50176>>>(ow, ob, (float*)d_out);
}

// round 3
// speedup vs baseline: 2.5544x; 2.5544x over previous
#include <cuda_runtime.h>
#include <cuda_bf16.h>

// Problem constants
#define TT 64
#define SS 64
#define BZ 128
#define EE 64
#define HH 4
#define HD 16

// Scratch (device globals; allocation-free)
__device__ __nv_bfloat16 g_wrel[128 * 64];            // rel_weight in bf16, [n][k]
__device__ float g_q[TT * BZ * EE];                   // q+bias+rel_bias  [i][b][e]
__device__ float g_k[SS * BZ * EE];                   // k+bias+rel_bias  [j][b][e]
__device__ float g_v[SS * BZ * EE];                   // [j][b][e]
__device__ float g_logits[BZ * TT * HH * SS];         // [b][i][h][j]

// ---------------------------------------------------------------------------
// Kernel 0: convert rel_weight fp32 [128][64] -> bf16 scratch
// ---------------------------------------------------------------------------
__global__ void k_convw(const float* __restrict__ w) {
    int t = threadIdx.x;
    #pragma unroll
    for (int it = 0; it < 32; ++it) {
        int idx = it * 256 + t;          // 8192 elements
        g_wrel[idx] = __float2bfloat16(w[idx]);
    }
}

// ---------------------------------------------------------------------------
// Kernel 1: q/k/v projections (fp32 scalar; exact). rel_bias folded into q,k.
// Block: 256 threads handles 64 rows. Grid: 128 blocks.
// ---------------------------------------------------------------------------
__global__ __launch_bounds__(256) void k_qkv(
    const float* __restrict__ xq, const float* __restrict__ xk,
    const float* __restrict__ xv, const float* __restrict__ W,
    const float* __restrict__ bias, const float* __restrict__ rbias)
{
    extern __shared__ float sm1[];
    float* Ws  = sm1;               // [64 f][192 eo]  (transposed weights)
    float* xsq = sm1 + 64 * 192;    // [64][64]
    float* xsk = xsq + 64 * 64;
    float* xsv = xsk + 64 * 64;

    int t  = threadIdx.x;
    int r0 = blockIdx.x * 64;

    // stage W transposed: W[eo][f] -> Ws[f*192 + eo]   (12288 floats)
    for (int it = 0; it < 48; ++it) {
        int idx = it * 256 + t;
        int eo = idx >> 6, f = idx & 63;
        Ws[f * 192 + eo] = W[idx];
    }
    // stage x tiles (4096 floats each), contiguous float4
    {
        const float4* q4 = (const float4*)(xq + r0 * 64);
        const float4* k4 = (const float4*)(xk + r0 * 64);
        const float4* v4 = (const float4*)(xv + r0 * 64);
        for (int it = 0; it < 4; ++it) {
            int idx = it * 256 + t;          // 1024 float4
            ((float4*)xsq)[idx] = q4[idx];
            ((float4*)xsk)[idx] = k4[idx];
            ((float4*)xsv)[idx] = v4[idx];
        }
    }
    __syncthreads();

    int e = t & 63, rg = t >> 6;  // e: output col, rg: row group (16 rows)
    float aq[16], ak[16], av[16];
    #pragma unroll
    for (int r = 0; r < 16; ++r) { aq[r] = 0.f; ak[r] = 0.f; av[r] = 0.f; }

    for (int f4 = 0; f4 < 16; ++f4) {
        int f0 = f4 * 4;
        float wq[4], wk[4], wv[4];
        #pragma unroll
        for (int ff = 0; ff < 4; ++ff) {
            wq[ff] = Ws[(f0 + ff) * 192 + e];
            wk[ff] = Ws[(f0 + ff) * 192 + 64 + e];
            wv[ff] = Ws[(f0 + ff) * 192 + 128 + e];
        }
        #pragma unroll
        for (int r = 0; r < 16; ++r) {
            int row = rg * 16 + r;
            float4 x4;
            x4 = *(const float4*)&xsq[row * 64 + f0];
            aq[r] += x4.x * wq[0] + x4.y * wq[1] + x4.z * wq[2] + x4.w * wq[3];
            x4 = *(const float4*)&xsk[row * 64 + f0];
            ak[r] += x4.x * wk[0] + x4.y * wk[1] + x4.z * wk[2] + x4.w * wk[3];
            x4 = *(const float4*)&xsv[row * 64 + f0];
            av[r] += x4.x * wv[0] + x4.y * wv[1] + x4.z * wv[2] + x4.w * wv[3];
        }
    }
    float bq = bias[e] + rbias[e];          // fold rel_bias[:64] into q
    float bk = bias[64 + e] + rbias[64 + e]; // fold rel_bias[64:] into k
    float bv = bias[128 + e];
    #pragma unroll
    for (int r = 0; r < 16; ++r) {
        int row = r0 + rg * 16 + r;
        g_q[row * 64 + e] = aq[r] + bq;
        g_k[row * 64 + e] = ak[r] + bk;
        g_v[row * 64 + e] = av[r] + bv;
    }
}

// ---------------------------------------------------------------------------
// Kernel 2 (main): fused relation GEMM (bf16 mma.sync) + logits epilogue.
// One CTA per (x=j, y=i) pair; M=128 (b), N=128 (2E), K=64.
// Accumulators initialized with q'/k' so fragments hold (q'+A), (k'+B).
// Per-head dots done in registers + quad shuffles. One __syncthreads total.
// ---------------------------------------------------------------------------
__device__ __forceinline__ void mma16816(float c[4], const unsigned a[4],
                                         const unsigned b[2]) {
    asm volatile(
        "mma.sync.aligned.m16n8k16.row.col.f32.bf16.bf16.f32 "
        "{%0,%1,%2,%3}, {%4,%5,%6,%7}, {%8,%9}, {%0,%1,%2,%3};\n"
        : "+f"(c[0]), "+f"(c[1]), "+f"(c[2]), "+f"(c[3])
        : "r"(a[0]), "r"(a[1]), "r"(a[2]), "r"(a[3]), "r"(b[0]), "r"(b[1]));
}

__global__ __launch_bounds__(256, 2) void k_rel(const float* __restrict__ rel)
{
    extern __shared__ char smraw[];
    unsigned* As32 = (unsigned*)smraw;          // [128 b][36] words, bf16 rel tile
    unsigned* Bs32 = As32 + 128 * 36;           // [128 n][36] words, bf16 weights
    float* qs = (float*)(Bs32 + 128 * 36);      // [128 b][68] q'
    float* ks = qs + 128 * 68;                  // [128 b][68] k'

    int t = threadIdx.x;
    int x = blockIdx.x >> 6;     // j
    int y = blockIdx.x & 63;     // i

    // Load relation tile: 8192 contiguous fp32 -> bf16 in SMEM
    const float4* rp = (const float4*)(rel + (size_t)blockIdx.x * 8192);
    #pragma unroll
    for (int it = 0; it < 8; ++it) {
        float4 v = rp[it * 256 + t];
        int fidx = (it * 256 + t) * 4;
        int row = fidx >> 6, kk = fidx & 63;
        __nv_bfloat162 p0 = __floats2bfloat162_rn(v.x, v.y);
        __nv_bfloat162 p1 = __floats2bfloat162_rn(v.z, v.w);
        As32[row * 36 + (kk >> 1)]     = *(unsigned*)&p0;
        As32[row * 36 + (kk >> 1) + 1] = *(unsigned*)&p1;
    }
    // bf16 weights: 4096 words (L2-hot)
    const unsigned* wp = (const unsigned*)g_wrel;
    #pragma unroll
    for (int it = 0; it < 16; ++it) {
        int idx = it * 256 + t;
        Bs32[(idx >> 5) * 36 + (idx & 31)] = wp[idx];
    }
    // Stage q'(y) and k'(x): 32KB each, contiguous float4
    {
        const float4* qp = (const float4*)(g_q + y * 8192);
        const float4* kp = (const float4*)(g_k + x * 8192);
        #pragma unroll
        for (int it = 0; it < 8; ++it) {
            int idx4 = it * 256 + t;
            int fidx = idx4 * 4;
            int row = fidx >> 6, col = fidx & 63;
            *(float4*)&qs[row * 68 + col] = qp[idx4];
            *(float4*)&ks[row * 68 + col] = kp[idx4];
        }
    }
    __syncthreads();

    // Warp wm covers rows 16*wm..16*wm+15 (b), all 128 cols (nt 0..15)
    int warp = t >> 5, lane = t & 31;
    int lr = lane >> 2, lc = lane & 3;
    int rbase = warp * 16;

    float c[16][4];
    // init accumulators: nt<8 from q' (cols 0..63), nt>=8 from k' (cols 64..127)
    #pragma unroll
    for (int nt = 0; nt < 8; ++nt) {
        int col = nt * 8 + 2 * lc;
        float2 lo = *(float2*)&qs[(rbase + lr) * 68 + col];
        float2 hi = *(float2*)&qs[(rbase + lr + 8) * 68 + col];
        c[nt][0] = lo.x; c[nt][1] = lo.y; c[nt][2] = hi.x; c[nt][3] = hi.y;
    }
    #pragma unroll
    for (int nt = 0; nt < 8; ++nt) {
        int col = nt * 8 + 2 * lc;
        float2 lo = *(float2*)&ks[(rbase + lr) * 68 + col];
        float2 hi = *(float2*)&ks[(rbase + lr + 8) * 68 + col];
        c[8 + nt][0] = lo.x; c[8 + nt][1] = lo.y;
        c[8 + nt][2] = hi.x; c[8 + nt][3] = hi.y;
    }

    #pragma unroll
    for (int kk = 0; kk < 4; ++kk) {
        int k0w = kk * 8;
        unsigned a[4];
        a[0] = As32[(rbase + lr) * 36 + k0w + lc];
        a[1] = As32[(rbase + lr + 8) * 36 + k0w + lc];
        a[2] = As32[(rbase + lr) * 36 + k0w + lc + 4];
        a[3] = As32[(rbase + lr + 8) * 36 + k0w + lc + 4];
        #pragma unroll
        for (int nt = 0; nt < 16; ++nt) {
            unsigned b[2];
            b[0] = Bs32[(nt * 8 + lr) * 36 + k0w + lc];
            b[1] = Bs32[(nt * 8 + lr) * 36 + k0w + lc + 4];
            mma16816(c[nt], a, b);
        }
    }

    // Register epilogue: logit[b][h] = (1/16) * sum_{n=0..15} P[b,hn] * Q[b,hn]
    // P = c[2h..2h+1], Q = c[8+2h..8+2h+1]; quad (lc) reduce via shfl.
    #pragma unroll
    for (int h = 0; h < 4; ++h) {
        float s0 = 0.f, s1 = 0.f;
        #pragma unroll
        for (int d = 0; d < 2; ++d) {
            int pa = 2 * h + d, pb = 8 + 2 * h + d;
            s0 += c[pa][0] * c[pb][0] + c[pa][1] * c[pb][1];
            s1 += c[pa][2] * c[pb][2] + c[pa][3] * c[pb][3];
        }
        s0 += __shfl_xor_sync(0xffffffffu, s0, 1);
        s0 += __shfl_xor_sync(0xffffffffu, s0, 2);
        s1 += __shfl_xor_sync(0xffffffffu, s1, 1);
        s1 += __shfl_xor_sync(0xffffffffu, s1, 2);
        if (lc == h) {
            int b0r = rbase + lr;
            int b1r = rbase + lr + 8;
            g_logits[(((size_t)b0r * 64 + y) * 4 + h) * 64 + x] = s0 * 0.0625f;
            g_logits[(((size_t)b1r * 64 + y) * 4 + h) * 64 + x] = s1 * 0.0625f;
        }
    }
}

// ---------------------------------------------------------------------------
// Kernel 3: softmax over j + AV + out-projection. Block per b (128 blocks),
// 256 threads = (i 64) x (h 4). Logits now contiguous per (b,i,h).
// ---------------------------------------------------------------------------
__global__ __launch_bounds__(256) void k_av(
    const float* __restrict__ Wo, const float* __restrict__ bo,
    float* __restrict__ out)
{
    extern __shared__ float sm3[];
    float* vs   = sm3;            // [64 x][64 e]
    float* Wos  = sm3 + 4096;     // [64 f][64 e]  (transposed out_weight)
    float* attn = sm3 + 8192;     // [64 i][68]

    int t = threadIdx.x;
    int b = blockIdx.x;

    for (int it = 0; it < 16; ++it) {
        int idx = it * 256 + t;   // 4096
        int xr = idx >> 6, e = idx & 63;
        vs[idx] = g_v[((size_t)xr * 128 + b) * 64 + e];
        Wos[e * 64 + xr] = Wo[idx];   // Wo[eo][f]: xr=eo, e=f -> Wos[f][eo]
    }
    __syncthreads();

    int h = t & 3, i = t >> 2;

    // softmax over j, per (i, b, h) — contiguous 64-float row
    float l[64];
    const float4* lp = (const float4*)(g_logits + (((size_t)b * 64 + i) * 4 + h) * 64);
    #pragma unroll
    for (int g = 0; g < 16; ++g) {
        float4 v4 = lp[g];
        l[4 * g] = v4.x; l[4 * g + 1] = v4.y; l[4 * g + 2] = v4.z; l[4 * g + 3] = v4.w;
    }
    float m = l[0];
    #pragma unroll
    for (int xj = 1; xj < 64; ++xj) m = fmaxf(m, l[xj]);
    float ssum = 0.f;
    #pragma unroll
    for (int xj = 0; xj < 64; ++xj) { l[xj] = __expf(l[xj] - m); ssum += l[xj]; }
    float inv = 1.f / ssum;

    // AV: acc[n] = sum_x w[x] * v[x][h*16+n]
    float acc[16];
    #pragma unroll
    for (int n = 0; n < 16; ++n) acc[n] = 0.f;
    for (int xj = 0; xj < 64; ++xj) {
        float wv = l[xj] * inv;
        const float4* vp = (const float4*)&vs[xj * 64 + h * 16];
        #pragma unroll
        for (int g = 0; g < 4; ++g) {
            float4 vv = vp[g];
            acc[4 * g + 0] += wv * vv.x;
            acc[4 * g + 1] += wv * vv.y;
            acc[4 * g + 2] += wv * vv.z;
            acc[4 * g + 3] += wv * vv.w;
        }
    }
    float* ap = &attn[i * 68 + h * 16];
    #pragma unroll
    for (int g = 0; g < 4; ++g)
        *(float4*)&ap[4 * g] = make_float4(acc[4 * g], acc[4 * g + 1],
                                           acc[4 * g + 2], acc[4 * g + 3]);
    __syncthreads();

    // out projection: out[i][b][e] = sum_f attn[i][f] * Wo[e][f] + bo[e]
    int i2 = t >> 2, eg = t & 3;
    float oacc[16];
    #pragma unroll
    for (int n = 0; n < 16; ++n) oacc[n] = 0.f;
    for (int f = 0; f < 64; ++f) {
        float a = attn[i2 * 68 + f];
        const float4* wp4 = (const float4*)&Wos[f * 64 + eg * 16];
        #pragma unroll
        for (int g = 0; g < 4; ++g) {
            float4 w4 = wp4[g];
            oacc[4 * g + 0] += a * w4.x;
            oacc[4 * g + 1] += a * w4.y;
            oacc[4 * g + 2] += a * w4.z;
            oacc[4 * g + 3] += a * w4.w;
        }
    }
    float* op = out + ((size_t)i2 * 128 + b) * 64 + eg * 16;
    #pragma unroll
    for (int n = 0; n < 16; ++n) op[n] = oacc[n] + bo[eg * 16 + n];
}

// ---------------------------------------------------------------------------
extern "C" void kernel_launch(void* const* d_in, const int* in_sizes, int n_in,
                              void* d_out, int out_size) {
    const float* q_in = (const float*)d_in[0];
    const float* k_in = (const float*)d_in[1];
    const float* v_in = (const float*)d_in[2];
    const float* rel  = (const float*)d_in[3];
    const float* ipw  = (const float*)d_in[4];
    const float* ipb  = (const float*)d_in[5];
    const float* rw   = (const float*)d_in[6];
    const float* rb   = (const float*)d_in[7];
    const float* ow   = (const float*)d_in[8];
    const float* ob   = (const float*)d_in[9];

    cudaFuncSetAttribute(k_qkv, cudaFuncAttributeMaxDynamicSharedMemorySize, 98304);
    cudaFuncSetAttribute(k_rel, cudaFuncAttributeMaxDynamicSharedMemorySize, 106496);
    cudaFuncSetAttribute(k_av,  cudaFuncAttributeMaxDynamicSharedMemorySize, 50176);

    k_convw<<<1, 256>>>(rw);
    k_qkv<<<128, 256, 98304>>>(q_in, k_in, v_in, ipw, ipb, rb);
    k_rel<<<4096, 256, 106496>>>(rel);
    k_av<<<128, 256, 50176>>>(ow, ob, (float*)d_out);
}

// round 6
// speedup vs baseline: 2.6974x; 1.0560x over previous
#include <cuda_runtime.h>
#include <cuda_bf16.h>
#include <cstdint>

// Problem constants: T=S=64, B=128, E=64, H=4, hd=16
#define TT 64
#define SS 64
#define BZ 128

// Scratch (device globals; allocation-free)
__device__ __nv_bfloat16 g_wrel[128 * 64];            // rel_weight bf16 [n][k]
__device__ float g_q[TT * BZ * 64];                   // q+bias+rel_bias [i][b][e]
__device__ float g_k[SS * BZ * 64];                   // k+bias+rel_bias [j][b][e]
__device__ float g_v[SS * BZ * 64];                   // [j][b][e]
__device__ float g_logits[BZ * TT * 4 * SS];          // [b][i][h][j]

// ---------------------------------------------------------------------------
// Kernel 1: q/k/v projections (fp32 scalar; exact). rel_bias folded into q,k.
// Block 0 additionally converts rel_weight -> g_wrel (bf16).
// ---------------------------------------------------------------------------
__global__ __launch_bounds__(256) void k_qkv(
    const float* __restrict__ xq, const float* __restrict__ xk,
    const float* __restrict__ xv, const float* __restrict__ W,
    const float* __restrict__ bias, const float* __restrict__ rbias,
    const float* __restrict__ rw)
{
    extern __shared__ float sm1[];
    float* Ws  = sm1;               // [64 f][192 eo]
    float* xsq = sm1 + 64 * 192;
    float* xsk = xsq + 64 * 64;
    float* xsv = xsk + 64 * 64;

    int t  = threadIdx.x;
    int r0 = blockIdx.x * 64;

    if (blockIdx.x == 0) {          // rel_weight fp32 -> bf16
        #pragma unroll
        for (int it = 0; it < 32; ++it) {
            int idx = it * 256 + t;
            g_wrel[idx] = __float2bfloat16(rw[idx]);
        }
    }

    for (int it = 0; it < 48; ++it) {
        int idx = it * 256 + t;
        int eo = idx >> 6, f = idx & 63;
        Ws[f * 192 + eo] = W[idx];
    }
    {
        const float4* q4 = (const float4*)(xq + r0 * 64);
        const float4* k4 = (const float4*)(xk + r0 * 64);
        const float4* v4 = (const float4*)(xv + r0 * 64);
        for (int it = 0; it < 4; ++it) {
            int idx = it * 256 + t;
            ((float4*)xsq)[idx] = q4[idx];
            ((float4*)xsk)[idx] = k4[idx];
            ((float4*)xsv)[idx] = v4[idx];
        }
    }
    __syncthreads();

    int e = t & 63, rg = t >> 6;
    float aq[16], ak[16], av[16];
    #pragma unroll
    for (int r = 0; r < 16; ++r) { aq[r] = 0.f; ak[r] = 0.f; av[r] = 0.f; }

    for (int f4 = 0; f4 < 16; ++f4) {
        int f0 = f4 * 4;
        float wq[4], wk[4], wv[4];
        #pragma unroll
        for (int ff = 0; ff < 4; ++ff) {
            wq[ff] = Ws[(f0 + ff) * 192 + e];
            wk[ff] = Ws[(f0 + ff) * 192 + 64 + e];
            wv[ff] = Ws[(f0 + ff) * 192 + 128 + e];
        }
        #pragma unroll
        for (int r = 0; r < 16; ++r) {
            int row = rg * 16 + r;
            float4 x4;
            x4 = *(const float4*)&xsq[row * 64 + f0];
            aq[r] += x4.x * wq[0] + x4.y * wq[1] + x4.z * wq[2] + x4.w * wq[3];
            x4 = *(const float4*)&xsk[row * 64 + f0];
            ak[r] += x4.x * wk[0] + x4.y * wk[1] + x4.z * wk[2] + x4.w * wk[3];
            x4 = *(const float4*)&xsv[row * 64 + f0];
            av[r] += x4.x * wv[0] + x4.y * wv[1] + x4.z * wv[2] + x4.w * wv[3];
        }
    }
    float bq = bias[e] + rbias[e];
    float bk = bias[64 + e] + rbias[64 + e];
    float bv = bias[128 + e];
    #pragma unroll
    for (int r = 0; r < 16; ++r) {
        int row = r0 + rg * 16 + r;
        g_q[row * 64 + e] = aq[r] + bq;
        g_k[row * 64 + e] = ak[r] + bk;
        g_v[row * 64 + e] = av[r] + bv;
    }
}

// ---------------------------------------------------------------------------
// Kernel 2 (main): fused relation GEMM (bf16 mma.sync) + incremental epilogue.
// One CTA per (x=j, y=i). A = rel tile [128 b][64 k] bf16, B = rel_weight
// [128 n][64 k] bf16 (both SMEM, stride 36 words = conflict-free).
// Per warp: 16 b-rows. Loop over 8 col-blocks nt: accumulators c_A (q'+A),
// c_B (k'+B) initialized straight from global (L2-hot), 4 K-step MMAs each,
// then fold c_A*c_B into per-head logit partials and recycle registers.
// ---------------------------------------------------------------------------
__device__ __forceinline__ void mma16816(float c[4], const unsigned a[4],
                                         const unsigned b[2]) {
    asm volatile(
        "mma.sync.aligned.m16n8k16.row.col.f32.bf16.bf16.f32 "
        "{%0,%1,%2,%3}, {%4,%5,%6,%7}, {%8,%9}, {%0,%1,%2,%3};\n"
        : "+f"(c[0]), "+f"(c[1]), "+f"(c[2]), "+f"(c[3])
        : "r"(a[0]), "r"(a[1]), "r"(a[2]), "r"(a[3]), "r"(b[0]), "r"(b[1]));
}

__global__ __launch_bounds__(256, 4) void k_rel(const float* __restrict__ rel)
{
    extern __shared__ unsigned smw[];
    unsigned* As32 = smw;               // [128 b][36] words, bf16 rel tile
    unsigned* Bs32 = smw + 128 * 36;    // [128 n][36] words, bf16 weights

    int t = threadIdx.x;
    int x = blockIdx.x >> 6;     // j
    int y = blockIdx.x & 63;     // i

    // A: rel tile, 2048 float4 contiguous -> bf16 in SMEM
    const float4* rp = (const float4*)(rel + (size_t)blockIdx.x * 8192);
    #pragma unroll
    for (int it = 0; it < 8; ++it) {
        int idx4 = it * 256 + t;
        float4 v = rp[idx4];
        int fidx = idx4 * 4;
        int row = fidx >> 6, kk = fidx & 63;
        __nv_bfloat162 p0 = __floats2bfloat162_rn(v.x, v.y);
        __nv_bfloat162 p1 = __floats2bfloat162_rn(v.z, v.w);
        As32[row * 36 + (kk >> 1)]     = *(unsigned*)&p0;
        As32[row * 36 + (kk >> 1) + 1] = *(unsigned*)&p1;
    }
    // B: weights bf16 (L2-hot), 4096 words
    const unsigned* wp = (const unsigned*)g_wrel;
    #pragma unroll
    for (int it = 0; it < 16; ++it) {
        int idx = it * 256 + t;
        Bs32[(idx >> 5) * 36 + (idx & 31)] = wp[idx];
    }
    __syncthreads();

    int warp = t >> 5, lane = t & 31;
    int lr = lane >> 2, lc = lane & 3;
    int rbase = warp * 16;

    const float* qbase = g_q + (size_t)(y * 128 + rbase) * 64;
    const float* kbase = g_k + (size_t)(x * 128 + rbase) * 64;

    float s[4][2];
    #pragma unroll
    for (int h = 0; h < 4; ++h) { s[h][0] = 0.f; s[h][1] = 0.f; }

    #pragma unroll
    for (int nt = 0; nt < 8; ++nt) {
        int col = nt * 8 + 2 * lc;
        float2 qlo = *(const float2*)(qbase + lr * 64 + col);
        float2 qhi = *(const float2*)(qbase + (lr + 8) * 64 + col);
        float2 klo = *(const float2*)(kbase + lr * 64 + col);
        float2 khi = *(const float2*)(kbase + (lr + 8) * 64 + col);
        float cA[4] = { qlo.x, qlo.y, qhi.x, qhi.y };
        float cB[4] = { klo.x, klo.y, khi.x, khi.y };

        #pragma unroll
        for (int kk = 0; kk < 4; ++kk) {
            int k0w = kk * 8;
            unsigned a[4];
            a[0] = As32[(rbase + lr) * 36 + k0w + lc];
            a[1] = As32[(rbase + lr + 8) * 36 + k0w + lc];
            a[2] = As32[(rbase + lr) * 36 + k0w + lc + 4];
            a[3] = As32[(rbase + lr + 8) * 36 + k0w + lc + 4];
            unsigned bA[2], bB[2];
            bA[0] = Bs32[(nt * 8 + lr) * 36 + k0w + lc];
            bA[1] = Bs32[(nt * 8 + lr) * 36 + k0w + lc + 4];
            bB[0] = Bs32[(64 + nt * 8 + lr) * 36 + k0w + lc];
            bB[1] = Bs32[(64 + nt * 8 + lr) * 36 + k0w + lc + 4];
            mma16816(cA, a, bA);
            mma16816(cB, a, bB);
        }
        int h = nt >> 1;
        s[h][0] += cA[0] * cB[0] + cA[1] * cB[1];
        s[h][1] += cA[2] * cB[2] + cA[3] * cB[3];
    }

    // quad reduce + store: lane with lc==h writes rows rbase+lr, rbase+lr+8
    #pragma unroll
    for (int h = 0; h < 4; ++h) {
        float s0 = s[h][0], s1 = s[h][1];
        s0 += __shfl_xor_sync(0xffffffffu, s0, 1);
        s0 += __shfl_xor_sync(0xffffffffu, s0, 2);
        s1 += __shfl_xor_sync(0xffffffffu, s1, 1);
        s1 += __shfl_xor_sync(0xffffffffu, s1, 2);
        if (lc == h) {
            int b0r = rbase + lr;
            int b1r = rbase + lr + 8;
            g_logits[((size_t)(b0r * 64 + y) * 4 + h) * 64 + x] = s0 * 0.0625f;
            g_logits[((size_t)(b1r * 64 + y) * 4 + h) * 64 + x] = s1 * 0.0625f;
        }
    }
}

// ---------------------------------------------------------------------------
// Kernel 3: softmax over j + AV + out-projection.
// Grid 256 = (b, i-half); 256 threads. softmax/AV: t -> (jh, h, il); pairs
// combine via shfl. Out-proj: t -> (il, e-group of 8).
// ---------------------------------------------------------------------------
__global__ __launch_bounds__(256) void k_av(
    const float* __restrict__ Wo, const float* __restrict__ bo,
    float* __restrict__ out)
{
    extern __shared__ float sm3[];
    float* vs   = sm3;            // [64 j][64 e]
    float* Wos  = sm3 + 4096;     // [64 f][64 e]
    float* attn = sm3 + 8192;     // [32 i][68]

    int t = threadIdx.x;
    int b = blockIdx.x >> 1;
    int ihalf = blockIdx.x & 1;

    // stage v rows for this b, and Wo transposed; 1024 float4 / 256 thr
    #pragma unroll
    for (int it = 0; it < 4; ++it) {
        int idx4 = it * 256 + t;           // 0..1023
        int row = idx4 >> 4, c0 = (idx4 & 15) * 4;
        float4 vv = *(const float4*)(g_v + ((size_t)row * 128 + b) * 64 + c0);
        *(float4*)&vs[row * 64 + c0] = vv;
        float4 wv = *(const float4*)(Wo + row * 64 + c0);   // Wo[eo=row][f=c0..]
        Wos[(c0 + 0) * 64 + row] = wv.x;
        Wos[(c0 + 1) * 64 + row] = wv.y;
        Wos[(c0 + 2) * 64 + row] = wv.z;
        Wos[(c0 + 3) * 64 + row] = wv.w;
    }
    __syncthreads();

    int jh = t & 1, h = (t >> 1) & 3, il = t >> 3;   // il 0..31
    int i = ihalf * 32 + il;

    // softmax over j: each lane handles 32 contiguous logits, pair-combine
    float l[32];
    {
        const float4* lp = (const float4*)(g_logits +
                           (((size_t)b * 64 + i) * 4 + h) * 64 + jh * 32);
        #pragma unroll
        for (int g = 0; g < 8; ++g) {
            float4 v4 = lp[g];
            l[4*g] = v4.x; l[4*g+1] = v4.y; l[4*g+2] = v4.z; l[4*g+3] = v4.w;
        }
    }
    float m = l[0];
    #pragma unroll
    for (int jj = 1; jj < 32; ++jj) m = fmaxf(m, l[jj]);
    m = fmaxf(m, __shfl_xor_sync(0xffffffffu, m, 1));
    float ssum = 0.f;
    #pragma unroll
    for (int jj = 0; jj < 32; ++jj) { l[jj] = __expf(l[jj] - m); ssum += l[jj]; }
    ssum += __shfl_xor_sync(0xffffffffu, ssum, 1);
    float inv = 1.f / ssum;

    // AV over this lane's 32 j's
    float acc[16];
    #pragma unroll
    for (int n = 0; n < 16; ++n) acc[n] = 0.f;
    #pragma unroll 4
    for (int jj = 0; jj < 32; ++jj) {
        float wv = l[jj] * inv;
        const float4* vp = (const float4*)&vs[(jh * 32 + jj) * 64 + h * 16];
        #pragma unroll
        for (int g = 0; g < 4; ++g) {
            float4 vv = vp[g];
            acc[4*g+0] += wv * vv.x;
            acc[4*g+1] += wv * vv.y;
            acc[4*g+2] += wv * vv.z;
            acc[4*g+3] += wv * vv.w;
        }
    }
    #pragma unroll
    for (int n = 0; n < 16; ++n)
        acc[n] += __shfl_xor_sync(0xffffffffu, acc[n], 1);
    // each lane of the pair stores its half
    {
        float* ap = &attn[il * 68 + h * 16 + jh * 8];
        *(float4*)&ap[0] = make_float4(acc[jh*8+0], acc[jh*8+1], acc[jh*8+2], acc[jh*8+3]);
        *(float4*)&ap[4] = make_float4(acc[jh*8+4], acc[jh*8+5], acc[jh*8+6], acc[jh*8+7]);
    }
    __syncthreads();

    // out projection: t -> (il = t>>3, e0 = (t&7)*8); 8 outputs per thread
    int i2l = t >> 3, e0 = (t & 7) * 8;
    int i2 = ihalf * 32 + i2l;
    float oacc[8];
    #pragma unroll
    for (int n = 0; n < 8; ++n) oacc[n] = 0.f;
    #pragma unroll 4
    for (int f = 0; f < 64; ++f) {
        float a = attn[i2l * 68 + f];
        float4 w1 = *(const float4*)&Wos[f * 64 + e0];
        float4 w2 = *(const float4*)&Wos[f * 64 + e0 + 4];
        oacc[0] += a * w1.x; oacc[1] += a * w1.y;
        oacc[2] += a * w1.z; oacc[3] += a * w1.w;
        oacc[4] += a * w2.x; oacc[5] += a * w2.y;
        oacc[6] += a * w2.z; oacc[7] += a * w2.w;
    }
    float* op = out + ((size_t)i2 * 128 + b) * 64 + e0;
    #pragma unroll
    for (int n = 0; n < 8; ++n) op[n] = oacc[n] + bo[e0 + n];
}

// ---------------------------------------------------------------------------
extern "C" void kernel_launch(void* const* d_in, const int* in_sizes, int n_in,
                              void* d_out, int out_size) {
    const float* q_in = (const float*)d_in[0];
    const float* k_in = (const float*)d_in[1];
    const float* v_in = (const float*)d_in[2];
    const float* rel  = (const float*)d_in[3];
    const float* ipw  = (const float*)d_in[4];
    const float* ipb  = (const float*)d_in[5];
    const float* rw   = (const float*)d_in[6];
    const float* rb   = (const float*)d_in[7];
    const float* ow   = (const float*)d_in[8];
    const float* ob   = (const float*)d_in[9];

    cudaFuncSetAttribute(k_qkv, cudaFuncAttributeMaxDynamicSharedMemorySize, 98304);

    k_qkv<<<128, 256, 98304>>>(q_in, k_in, v_in, ipw, ipb, rb, rw);
    k_rel<<<4096, 256, 2 * 128 * 36 * 4>>>(rel);
    k_av<<<256, 256, (4096 + 4096 + 32 * 68) * 4>>>(ow, ob, (float*)d_out);
}

// round 8
// speedup vs baseline: 2.6992x; 1.0007x over previous
#include <cuda_runtime.h>
#include <cuda_bf16.h>
#include <cstdint>

// Problem constants: T=S=64, B=128, E=64, H=4, hd=16
#define TT 64
#define SS 64
#define BZ 128

// Scratch (device globals; allocation-free)
__device__ __nv_bfloat16 g_wrel[128 * 64];            // rel_weight bf16 [n][k]
__device__ float g_q[TT * BZ * 64];                   // q+bias+rel_bias [i][b][e]
__device__ float g_k[SS * BZ * 64];                   // k+bias+rel_bias [j][b][e]
__device__ float g_v[SS * BZ * 64];                   // [j][b][e]
__device__ float g_logits[BZ * TT * 4 * SS];          // [b][i][h][j]

// ---------------------------------------------------------------------------
// Kernel 1: q/k/v projections (fp32 scalar; exact). rel_bias folded into q,k.
// Block 0 additionally converts rel_weight -> g_wrel (bf16).
// ---------------------------------------------------------------------------
__global__ __launch_bounds__(256) void k_qkv(
    const float* __restrict__ xq, const float* __restrict__ xk,
    const float* __restrict__ xv, const float* __restrict__ W,
    const float* __restrict__ bias, const float* __restrict__ rbias,
    const float* __restrict__ rw)
{
    extern __shared__ float sm1[];
    float* Ws  = sm1;               // [64 f][192 eo]
    float* xsq = sm1 + 64 * 192;
    float* xsk = xsq + 64 * 64;
    float* xsv = xsk + 64 * 64;

    int t  = threadIdx.x;
    int r0 = blockIdx.x * 64;

    if (blockIdx.x == 0) {          // rel_weight fp32 -> bf16
        #pragma unroll
        for (int it = 0; it < 32; ++it) {
            int idx = it * 256 + t;
            g_wrel[idx] = __float2bfloat16(rw[idx]);
        }
    }

    for (int it = 0; it < 48; ++it) {
        int idx = it * 256 + t;
        int eo = idx >> 6, f = idx & 63;
        Ws[f * 192 + eo] = W[idx];
    }
    {
        const float4* q4 = (const float4*)(xq + r0 * 64);
        const float4* k4 = (const float4*)(xk + r0 * 64);
        const float4* v4 = (const float4*)(xv + r0 * 64);
        for (int it = 0; it < 4; ++it) {
            int idx = it * 256 + t;
            ((float4*)xsq)[idx] = q4[idx];
            ((float4*)xsk)[idx] = k4[idx];
            ((float4*)xsv)[idx] = v4[idx];
        }
    }
    __syncthreads();

    int e = t & 63, rg = t >> 6;
    float aq[16], ak[16], av[16];
    #pragma unroll
    for (int r = 0; r < 16; ++r) { aq[r] = 0.f; ak[r] = 0.f; av[r] = 0.f; }

    for (int f4 = 0; f4 < 16; ++f4) {
        int f0 = f4 * 4;
        float wq[4], wk[4], wv[4];
        #pragma unroll
        for (int ff = 0; ff < 4; ++ff) {
            wq[ff] = Ws[(f0 + ff) * 192 + e];
            wk[ff] = Ws[(f0 + ff) * 192 + 64 + e];
            wv[ff] = Ws[(f0 + ff) * 192 + 128 + e];
        }
        #pragma unroll
        for (int r = 0; r < 16; ++r) {
            int row = rg * 16 + r;
            float4 x4;
            x4 = *(const float4*)&xsq[row * 64 + f0];
            aq[r] += x4.x * wq[0] + x4.y * wq[1] + x4.z * wq[2] + x4.w * wq[3];
            x4 = *(const float4*)&xsk[row * 64 + f0];
            ak[r] += x4.x * wk[0] + x4.y * wk[1] + x4.z * wk[2] + x4.w * wk[3];
            x4 = *(const float4*)&xsv[row * 64 + f0];
            av[r] += x4.x * wv[0] + x4.y * wv[1] + x4.z * wv[2] + x4.w * wv[3];
        }
    }
    float bq = bias[e] + rbias[e];
    float bk = bias[64 + e] + rbias[64 + e];
    float bv = bias[128 + e];
    #pragma unroll
    for (int r = 0; r < 16; ++r) {
        int row = r0 + rg * 16 + r;
        g_q[row * 64 + e] = aq[r] + bq;
        g_k[row * 64 + e] = ak[r] + bk;
        g_v[row * 64 + e] = av[r] + bv;
    }
}

// ---------------------------------------------------------------------------
// Kernel 2 (main): fused relation GEMM (bf16 mma.sync) + incremental epilogue.
// One CTA per (x=j, y=i). A = rel tile [128 b][64 k] bf16, B = rel_weight
// [128 n][64 k] bf16 (both SMEM, stride 36 words = conflict-free).
// Per warp: 16 b-rows. Loop over 8 col-blocks nt: accumulators c_A (q'+A),
// c_B (k'+B) initialized straight from global (L2-hot), 4 K-step MMAs each,
// then fold c_A*c_B into per-head logit partials and recycle registers.
// ---------------------------------------------------------------------------
__device__ __forceinline__ void mma16816(float c[4], const unsigned a[4],
                                         const unsigned b[2]) {
    asm volatile(
        "mma.sync.aligned.m16n8k16.row.col.f32.bf16.bf16.f32 "
        "{%0,%1,%2,%3}, {%4,%5,%6,%7}, {%8,%9}, {%0,%1,%2,%3};\n"
        : "+f"(c[0]), "+f"(c[1]), "+f"(c[2]), "+f"(c[3])
        : "r"(a[0]), "r"(a[1]), "r"(a[2]), "r"(a[3]), "r"(b[0]), "r"(b[1]));
}

__global__ __launch_bounds__(256, 4) void k_rel(const float* __restrict__ rel)
{
    extern __shared__ unsigned smw[];
    unsigned* As32 = smw;               // [128 b][36] words, bf16 rel tile
    unsigned* Bs32 = smw + 128 * 36;    // [128 n][36] words, bf16 weights

    int t = threadIdx.x;
    int x = blockIdx.x >> 6;     // j
    int y = blockIdx.x & 63;     // i

    // A: rel tile, 2048 float4 contiguous -> bf16 in SMEM
    const float4* rp = (const float4*)(rel + (size_t)blockIdx.x * 8192);
    #pragma unroll
    for (int it = 0; it < 8; ++it) {
        int idx4 = it * 256 + t;
        float4 v = rp[idx4];
        int fidx = idx4 * 4;
        int row = fidx >> 6, kk = fidx & 63;
        __nv_bfloat162 p0 = __floats2bfloat162_rn(v.x, v.y);
        __nv_bfloat162 p1 = __floats2bfloat162_rn(v.z, v.w);
        As32[row * 36 + (kk >> 1)]     = *(unsigned*)&p0;
        As32[row * 36 + (kk >> 1) + 1] = *(unsigned*)&p1;
    }
    // B: weights bf16 (L2-hot), 4096 words
    const unsigned* wp = (const unsigned*)g_wrel;
    #pragma unroll
    for (int it = 0; it < 16; ++it) {
        int idx = it * 256 + t;
        Bs32[(idx >> 5) * 36 + (idx & 31)] = wp[idx];
    }
    __syncthreads();

    int warp = t >> 5, lane = t & 31;
    int lr = lane >> 2, lc = lane & 3;
    int rbase = warp * 16;

    const float* qbase = g_q + (size_t)(y * 128 + rbase) * 64;
    const float* kbase = g_k + (size_t)(x * 128 + rbase) * 64;

    float s[4][2];
    #pragma unroll
    for (int h = 0; h < 4; ++h) { s[h][0] = 0.f; s[h][1] = 0.f; }

    #pragma unroll
    for (int nt = 0; nt < 8; ++nt) {
        int col = nt * 8 + 2 * lc;
        float2 qlo = *(const float2*)(qbase + lr * 64 + col);
        float2 qhi = *(const float2*)(qbase + (lr + 8) * 64 + col);
        float2 klo = *(const float2*)(kbase + lr * 64 + col);
        float2 khi = *(const float2*)(kbase + (lr + 8) * 64 + col);
        float cA[4] = { qlo.x, qlo.y, qhi.x, qhi.y };
        float cB[4] = { klo.x, klo.y, khi.x, khi.y };

        #pragma unroll
        for (int kk = 0; kk < 4; ++kk) {
            int k0w = kk * 8;
            unsigned a[4];
            a[0] = As32[(rbase + lr) * 36 + k0w + lc];
            a[1] = As32[(rbase + lr + 8) * 36 + k0w + lc];
            a[2] = As32[(rbase + lr) * 36 + k0w + lc + 4];
            a[3] = As32[(rbase + lr + 8) * 36 + k0w + lc + 4];
            unsigned bA[2], bB[2];
            bA[0] = Bs32[(nt * 8 + lr) * 36 + k0w + lc];
            bA[1] = Bs32[(nt * 8 + lr) * 36 + k0w + lc + 4];
            bB[0] = Bs32[(64 + nt * 8 + lr) * 36 + k0w + lc];
            bB[1] = Bs32[(64 + nt * 8 + lr) * 36 + k0w + lc + 4];
            mma16816(cA, a, bA);
            mma16816(cB, a, bB);
        }
        int h = nt >> 1;
        s[h][0] += cA[0] * cB[0] + cA[1] * cB[1];
        s[h][1] += cA[2] * cB[2] + cA[3] * cB[3];
    }

    // quad reduce + store: lane with lc==h writes rows rbase+lr, rbase+lr+8
    #pragma unroll
    for (int h = 0; h < 4; ++h) {
        float s0 = s[h][0], s1 = s[h][1];
        s0 += __shfl_xor_sync(0xffffffffu, s0, 1);
        s0 += __shfl_xor_sync(0xffffffffu, s0, 2);
        s1 += __shfl_xor_sync(0xffffffffu, s1, 1);
        s1 += __shfl_xor_sync(0xffffffffu, s1, 2);
        if (lc == h) {
            int b0r = rbase + lr;
            int b1r = rbase + lr + 8;
            g_logits[((size_t)(b0r * 64 + y) * 4 + h) * 64 + x] = s0 * 0.0625f;
            g_logits[((size_t)(b1r * 64 + y) * 4 + h) * 64 + x] = s1 * 0.0625f;
        }
    }
}

// ---------------------------------------------------------------------------
// Kernel 3: softmax over j + AV + out-projection.
// Grid 256 = (b, i-half); 256 threads. softmax/AV: t -> (jh, h, il); pairs
// combine via shfl. Out-proj: t -> (il, e-group of 8).
// ---------------------------------------------------------------------------
__global__ __launch_bounds__(256) void k_av(
    const float* __restrict__ Wo, const float* __restrict__ bo,
    float* __restrict__ out)
{
    extern __shared__ float sm3[];
    float* vs   = sm3;            // [64 j][64 e]
    float* Wos  = sm3 + 4096;     // [64 f][64 e]
    float* attn = sm3 + 8192;     // [32 i][68]

    int t = threadIdx.x;
    int b = blockIdx.x >> 1;
    int ihalf = blockIdx.x & 1;

    // stage v rows for this b, and Wo transposed; 1024 float4 / 256 thr
    #pragma unroll
    for (int it = 0; it < 4; ++it) {
        int idx4 = it * 256 + t;           // 0..1023
        int row = idx4 >> 4, c0 = (idx4 & 15) * 4;
        float4 vv = *(const float4*)(g_v + ((size_t)row * 128 + b) * 64 + c0);
        *(float4*)&vs[row * 64 + c0] = vv;
        float4 wv = *(const float4*)(Wo + row * 64 + c0);   // Wo[eo=row][f=c0..]
        Wos[(c0 + 0) * 64 + row] = wv.x;
        Wos[(c0 + 1) * 64 + row] = wv.y;
        Wos[(c0 + 2) * 64 + row] = wv.z;
        Wos[(c0 + 3) * 64 + row] = wv.w;
    }
    __syncthreads();

    int jh = t & 1, h = (t >> 1) & 3, il = t >> 3;   // il 0..31
    int i = ihalf * 32 + il;

    // softmax over j: each lane handles 32 contiguous logits, pair-combine
    float l[32];
    {
        const float4* lp = (const float4*)(g_logits +
                           (((size_t)b * 64 + i) * 4 + h) * 64 + jh * 32);
        #pragma unroll
        for (int g = 0; g < 8; ++g) {
            float4 v4 = lp[g];
            l[4*g] = v4.x; l[4*g+1] = v4.y; l[4*g+2] = v4.z; l[4*g+3] = v4.w;
        }
    }
    float m = l[0];
    #pragma unroll
    for (int jj = 1; jj < 32; ++jj) m = fmaxf(m, l[jj]);
    m = fmaxf(m, __shfl_xor_sync(0xffffffffu, m, 1));
    float ssum = 0.f;
    #pragma unroll
    for (int jj = 0; jj < 32; ++jj) { l[jj] = __expf(l[jj] - m); ssum += l[jj]; }
    ssum += __shfl_xor_sync(0xffffffffu, ssum, 1);
    float inv = 1.f / ssum;

    // AV over this lane's 32 j's
    float acc[16];
    #pragma unroll
    for (int n = 0; n < 16; ++n) acc[n] = 0.f;
    #pragma unroll 4
    for (int jj = 0; jj < 32; ++jj) {
        float wv = l[jj] * inv;
        const float4* vp = (const float4*)&vs[(jh * 32 + jj) * 64 + h * 16];
        #pragma unroll
        for (int g = 0; g < 4; ++g) {
            float4 vv = vp[g];
            acc[4*g+0] += wv * vv.x;
            acc[4*g+1] += wv * vv.y;
            acc[4*g+2] += wv * vv.z;
            acc[4*g+3] += wv * vv.w;
        }
    }
    #pragma unroll
    for (int n = 0; n < 16; ++n)
        acc[n] += __shfl_xor_sync(0xffffffffu, acc[n], 1);
    // each lane of the pair stores its half
    {
        float* ap = &attn[il * 68 + h * 16 + jh * 8];
        *(float4*)&ap[0] = make_float4(acc[jh*8+0], acc[jh*8+1], acc[jh*8+2], acc[jh*8+3]);
        *(float4*)&ap[4] = make_float4(acc[jh*8+4], acc[jh*8+5], acc[jh*8+6], acc[jh*8+7]);
    }
    __syncthreads();

    // out projection: t -> (il = t>>3, e0 = (t&7)*8); 8 outputs per thread
    int i2l = t >> 3, e0 = (t & 7) * 8;
    int i2 = ihalf * 32 + i2l;
    float oacc[8];
    #pragma unroll
    for (int n = 0; n < 8; ++n) oacc[n] = 0.f;
    #pragma unroll 4
    for (int f = 0; f < 64; ++f) {
        float a = attn[i2l * 68 + f];
        float4 w1 = *(const float4*)&Wos[f * 64 + e0];
        float4 w2 = *(const float4*)&Wos[f * 64 + e0 + 4];
        oacc[0] += a * w1.x; oacc[1] += a * w1.y;
        oacc[2] += a * w1.z; oacc[3] += a * w1.w;
        oacc[4] += a * w2.x; oacc[5] += a * w2.y;
        oacc[6] += a * w2.z; oacc[7] += a * w2.w;
    }
    float* op = out + ((size_t)i2 * 128 + b) * 64 + e0;
    #pragma unroll
    for (int n = 0; n < 8; ++n) op[n] = oacc[n] + bo[e0 + n];
}

// ---------------------------------------------------------------------------
extern "C" void kernel_launch(void* const* d_in, const int* in_sizes, int n_in,
                              void* d_out, int out_size) {
    const float* q_in = (const float*)d_in[0];
    const float* k_in = (const float*)d_in[1];
    const float* v_in = (const float*)d_in[2];
    const float* rel  = (const float*)d_in[3];
    const float* ipw  = (const float*)d_in[4];
    const float* ipb  = (const float*)d_in[5];
    const float* rw   = (const float*)d_in[6];
    const float* rb   = (const float*)d_in[7];
    const float* ow   = (const float*)d_in[8];
    const float* ob   = (const float*)d_in[9];

    cudaFuncSetAttribute(k_qkv, cudaFuncAttributeMaxDynamicSharedMemorySize, 98304);

    k_qkv<<<128, 256, 98304>>>(q_in, k_in, v_in, ipw, ipb, rb, rw);
    k_rel<<<4096, 256, 2 * 128 * 36 * 4>>>(rel);
    k_av<<<256, 256, (4096 + 4096 + 32 * 68) * 4>>>(ow, ob, (float*)d_out);
}